// round 15
// baseline (speedup 1.0000x reference)
#include <cuda_runtime.h>
#include <cuda.h>
#include <cuda_fp16.h>
#include <mma.h>
#include <stdint.h>
#include <math.h>
#include <dlfcn.h>
#include <string.h>

using namespace nvcuda;

#define NTOK 8192
#define DIM  1024
#define HID  4096
#define NE   8
#define BM   128
#define BN   256
#define GM   2
#define BNW  128
#define BK   32
#define LDSMW (BK + 8)
#define KC   32
#define STG  5
#define A_ST (GM * BM * KC * 2)         // 16384
#define B_ST (BN * KC * 2)              // 16384
#define STAGE_BYTES (A_ST + B_ST)       // 32768
#define PAD  (GM*BM)
#define MAXG (NTOK / BM / GM + NE)      // 40
#define MAXT (NTOK / BM + NE)
#define SMEM_BYTES (1024 + 1024 + STG * STAGE_BYTES)   // 165888
#define WTOT ((size_t)NE * HID * DIM)   // 33554432 per weight tensor
#define NCONV_UP 16384                  // Wup convert blocks (WTOT / 2048)
#define NRB (NTOK / 8)                  // router blocks = 1024
#define SLICE 57344                     // Wdown elems per UP-GEMM CTA (32 units x 224 thr x 8)

#if defined(__CUDA_ARCH_FEAT_SM103_ALL) || defined(__CUDA_ARCH_FEAT_SM100_ALL) || defined(__CUDA_ARCH_FEAT_SM101_ALL)
#define TC5 1
#else
#define TC5 0
#endif

// ---------------- device scratch ----------------
__device__ int    g_expert[NTOK];
__device__ int    g_count[NE];          // zero-init; scan re-zeroes after consuming
__device__ int    g_cursor[NE];         // zero-init; scan re-zeroes
__device__ int    g_done;               // router ticket; self-resetting
__device__ int    g_off[NE + 1];
__device__ int    g_perm[NTOK];
__device__ int    g_grp_e[MAXG];
__device__ int    g_grp_r0[MAXG];
__device__ int    g_grp_ng[MAXG];
__device__ int    g_tile_e[MAXT];
__device__ int    g_tile_r0[MAXT];
__device__ __half g_xg[(size_t)(NTOK + PAD) * DIM];
__device__ __half g_h [(size_t)(NTOK + PAD) * HID];
__device__ __half g_wup[WTOT];
__device__ __half g_wdn[WTOT];

// ---------------- PTX helpers ----------------
__device__ __forceinline__ uint32_t smem_u32(const void* p) {
    uint32_t a;
    asm("{ .reg .u64 t; cvta.to.shared.u64 t, %1; cvt.u32.u64 %0, t; }" : "=r"(a) : "l"(p));
    return a;
}
#if TC5
__device__ __forceinline__ bool elect1() {
    uint32_t r;
    asm volatile("{\n\t.reg .pred p;\n\telect.sync _|p, 0xFFFFFFFF;\n\tselp.b32 %0,1,0,p;\n\t}" : "=r"(r));
    return r != 0;
}
__device__ __forceinline__ void mbar_init(uint32_t a, uint32_t cnt) {
    asm volatile("mbarrier.init.shared.b64 [%0], %1;" :: "r"(a), "r"(cnt) : "memory");
}
__device__ __forceinline__ void mbar_wait(uint32_t a, uint32_t ph) {
    asm volatile(
        "{\n\t.reg .pred P;\n\t"
        "LW_%=:\n\t"
        "mbarrier.try_wait.parity.acquire.cta.shared::cta.b64 P, [%0], %1, 0x989680;\n\t"
        "@P bra LD_%=;\n\t"
        "bra LW_%=;\n\t"
        "LD_%=:\n\t}"
        :: "r"(a), "r"(ph) : "memory");
}
__device__ __forceinline__ void mbar_expect(uint32_t a, uint32_t bytes) {
    asm volatile("mbarrier.arrive.expect_tx.shared.b64 _, [%0], %1;"
                 :: "r"(a), "r"(bytes) : "memory");
}
__device__ __forceinline__ void tma2d(uint32_t dst, const void* map, int x, int y, uint32_t mbar) {
    asm volatile(
        "cp.async.bulk.tensor.2d.shared::cta.global.tile.mbarrier::complete_tx::bytes "
        "[%0], [%1, {%2, %3}], [%4];"
        :: "r"(dst), "l"(map), "r"(x), "r"(y), "r"(mbar) : "memory");
}
__device__ __forceinline__ void tmalloc(uint32_t smem_dst, uint32_t ncols) {
    asm volatile("tcgen05.alloc.cta_group::1.sync.aligned.shared::cta.b32 [%0], %1;"
                 :: "r"(smem_dst), "r"(ncols) : "memory");
}
__device__ __forceinline__ void tmdealloc(uint32_t tmem, uint32_t ncols) {
    asm volatile("tcgen05.relinquish_alloc_permit.cta_group::1.sync.aligned;");
    asm volatile("tcgen05.dealloc.cta_group::1.sync.aligned.b32 %0, %1;" :: "r"(tmem), "r"(ncols));
}
__device__ __forceinline__ void mma_f16_ss(uint32_t d, uint64_t ad, uint64_t bd, uint32_t idesc, uint32_t en) {
    asm volatile(
        "{\n\t.reg .pred p;\n\tsetp.ne.u32 p, %5, 0;\n\t"
        "tcgen05.mma.cta_group::1.kind::f16 [%0], %1, %2, %3, {%4,%4,%4,%4}, p;\n\t}"
        :: "r"(d), "l"(ad), "l"(bd), "r"(idesc), "r"(0u), "r"(en) : "memory");
}
__device__ __forceinline__ void tccommit(uint32_t mbar) {
    asm volatile("tcgen05.commit.cta_group::1.mbarrier::arrive::one.shared::cluster.b64 [%0];"
                 :: "r"(mbar) : "memory");
}
__device__ __forceinline__ void ldtm32(uint32_t* r, uint32_t addr) {
    asm volatile(
        "tcgen05.ld.sync.aligned.32x32b.x32.b32 "
        "{%0, %1, %2, %3, %4, %5, %6, %7, "
        " %8, %9, %10, %11, %12, %13, %14, %15, "
        " %16, %17, %18, %19, %20, %21, %22, %23, "
        " %24, %25, %26, %27, %28, %29, %30, %31}, [%32];"
        : "=r"(r[0]),  "=r"(r[1]),  "=r"(r[2]),  "=r"(r[3]),
          "=r"(r[4]),  "=r"(r[5]),  "=r"(r[6]),  "=r"(r[7]),
          "=r"(r[8]),  "=r"(r[9]),  "=r"(r[10]), "=r"(r[11]),
          "=r"(r[12]), "=r"(r[13]), "=r"(r[14]), "=r"(r[15]),
          "=r"(r[16]), "=r"(r[17]), "=r"(r[18]), "=r"(r[19]),
          "=r"(r[20]), "=r"(r[21]), "=r"(r[22]), "=r"(r[23]),
          "=r"(r[24]), "=r"(r[25]), "=r"(r[26]), "=r"(r[27]),
          "=r"(r[28]), "=r"(r[29]), "=r"(r[30]), "=r"(r[31])
        : "r"(addr));
}
#endif
// SW64 K-major descriptor: layout=4, SBO=32, LBO=1
__device__ __forceinline__ uint64_t mk_desc64(uint32_t addr) {
    return ((uint64_t)4 << 61) | ((uint64_t)1 << 46) | ((uint64_t)32 << 32) |
           ((uint64_t)1 << 16) | ((addr >> 4) & 0x3FFF);
}

__device__ __forceinline__ void cvt8(const float* src, __half* dst, size_t off) {
    float4 v0 = *(const float4*)(src + off);
    float4 v1 = *(const float4*)(src + off + 4);
    __half2 h[4];
    h[0] = __floats2half2_rn(v0.x, v0.y);
    h[1] = __floats2half2_rn(v0.z, v0.w);
    h[2] = __floats2half2_rn(v1.x, v1.y);
    h[3] = __floats2half2_rn(v1.z, v1.w);
    *(int4*)(dst + off) = *(int4*)h;
}

// ---------------- router + last-block inline scan (self-resetting) ----------------
__global__ void k_router(const float* __restrict__ x,
                         const float* __restrict__ Wr,
                         const float* __restrict__ br) {
    __shared__ float sW[NE * DIM];
    for (int i = threadIdx.x; i < NE * DIM; i += 256) sW[i] = Wr[i];
    __syncthreads();

    int warp = threadIdx.x >> 5, lane = threadIdx.x & 31;
    int t = blockIdx.x * 8 + warp;
    const float4* xr = (const float4*)(x + (size_t)t * DIM);

    float acc[NE];
#pragma unroll
    for (int e = 0; e < NE; e++) acc[e] = 0.f;
#pragma unroll
    for (int p = 0; p < 8; p++) {
        float4 v = xr[p * 32 + lane];
        int c = (p * 32 + lane) * 4;
#pragma unroll
        for (int e = 0; e < NE; e++) {
            const float* w = &sW[e * DIM + c];
            acc[e] += v.x * w[0] + v.y * w[1] + v.z * w[2] + v.w * w[3];
        }
    }
#pragma unroll
    for (int e = 0; e < NE; e++)
#pragma unroll
        for (int o = 16; o; o >>= 1) acc[e] += __shfl_xor_sync(0xffffffffu, acc[e], o);

    if (lane == 0) {
        int best = 0;
        float bv = acc[0] + br[0];
#pragma unroll
        for (int e = 1; e < NE; e++) {
            float v = acc[e] + br[e];
            if (v > bv) { bv = v; best = e; }
        }
        g_expert[t] = best;
        atomicAdd(&g_count[best], 1);
    }
    __syncthreads();
    if (threadIdx.x == 0) {
        __threadfence();
        int tk = atomicAdd(&g_done, 1);
        if (tk == NRB - 1) {
            int cnt[NE];
            int o = 0;
#pragma unroll
            for (int e = 0; e < NE; e++) {
                cnt[e] = g_count[e];
                g_off[e] = o;
                o += cnt[e];
            }
            g_off[NE] = o;
            int tg = 0;
            for (int e = 0; e < NE; e++) {
                int tiles = (cnt[e] + BM - 1) / BM;
                for (int m = 0; m < tiles; m += GM) {
                    g_grp_e[tg] = e;
                    g_grp_r0[tg] = g_off[e] + m * BM;
                    int rem = tiles - m;
                    g_grp_ng[tg] = rem < GM ? rem : GM;
                    tg++;
                }
            }
            for (; tg < MAXG; tg++) g_grp_e[tg] = -1;
            int tt = 0;
            for (int e = 0; e < NE; e++) {
                int tiles = (cnt[e] + BM - 1) / BM;
                for (int m = 0; m < tiles; m++) {
                    g_tile_e[tt] = e;
                    g_tile_r0[tt] = g_off[e] + m * BM;
                    tt++;
                }
            }
            for (; tt < MAXT; tt++) g_tile_e[tt] = -1;
#pragma unroll
            for (int e = 0; e < NE; e++) { g_count[e] = 0; g_cursor[e] = 0; }
            g_done = 0;
            __threadfence();
        }
    }
}

// ---------------- gather (blocks 0..NRB-1) + Wup convert (blocks behind) ----------------
__global__ void k_gather(const float* __restrict__ x, const float* __restrict__ Wup) {
    if (blockIdx.x >= NRB) {
        size_t base = ((size_t)(blockIdx.x - NRB) * 256 + threadIdx.x) * 8;
        cvt8(Wup, g_wup, base);
        return;
    }
    int gw = (blockIdx.x * blockDim.x + threadIdx.x) >> 5;
    int lane = threadIdx.x & 31;
    if (gw >= NTOK) return;
    int t = gw, e = g_expert[t];
    int slot = 0;
    if (lane == 0) {
        int r = atomicAdd(&g_cursor[e], 1);
        slot = g_off[e] + r;
        g_perm[slot] = t;
    }
    slot = __shfl_sync(0xffffffffu, slot, 0);
    const float4* src = (const float4*)(x + (size_t)t * DIM);
    __half2* dst = (__half2*)(g_xg + (size_t)slot * DIM);
#pragma unroll
    for (int p = 0; p < 8; p++) {
        float4 v = src[p * 32 + lane];
        dst[(p * 32 + lane) * 2]     = __floats2half2_rn(v.x, v.y);
        dst[(p * 32 + lane) * 2 + 1] = __floats2half2_rn(v.z, v.w);
    }
}

// ================= TMA tcgen05 GEMM: control thread + batched Wdown convert (UP) =================
template<int KTOT, bool UP>
__global__ void __launch_bounds__(256, 1) k_gemm(const __grid_constant__ CUtensorMap tmA,
                                                 const __grid_constant__ CUtensorMap tmB,
                                                 const float* __restrict__ bias,
                                                 float* __restrict__ out,
                                                 const float* __restrict__ wsrc) {
#if TC5
    extern __shared__ char smem_raw[];
    char* smem = (char*)(((uintptr_t)smem_raw + 1023) & ~(uintptr_t)1023);
    const int NOUT = UP ? HID : DIM;

    int gi = blockIdx.y;
    int e = g_grp_e[gi];
    bool active = (e >= 0);
    if (!UP && !active) return;
    int row0 = active ? g_grp_r0[gi] : 0;
    int ng   = active ? g_grp_ng[gi] : 0;
    int row_end = active ? g_off[e + 1] : 0;
    int n0 = blockIdx.x * BN;
    int tid = threadIdx.x, warp = tid >> 5, lane = tid & 31;
    uint32_t sb = smem_u32(smem);

    if (active) {
        if (tid == 0) {
#pragma unroll
            for (int j = 0; j < STG; j++) {
                mbar_init(sb + 8 * j, 1);
                mbar_init(sb + 64 + 8 * j, 1);
            }
        }
        if (warp == 0) tmalloc(sb + 128, 512);
    }
    __syncthreads();
    uint32_t tmem = 0;
    if (active)
        asm volatile("ld.shared.b32 %0, [%1];" : "=r"(tmem) : "r"(sb + 128));

    const uint32_t idesc = (1u << 4) | ((BN / 8) << 17) | ((BM / 16) << 24);
    const int SMA = 1024;
    const int NKC = KTOT / KC;
    const int brow0 = e * NOUT + n0;

    // ---- background duty (UP only): warps 1-7, 16-deep batched LDG convert ----
    if (UP && warp != 0) {
        int cta = blockIdx.y * gridDim.x + blockIdx.x;      // 0..639
        size_t base0 = (size_t)cta * SLICE;
        if (base0 < WTOT) {
            int wt = tid - 32;                              // 0..223
            if (base0 + SLICE <= WTOT) {
                const float4* s4 = (const float4*)(wsrc + base0);
                int4* d4 = (int4*)(g_wdn + base0);
#pragma unroll
                for (int blk = 0; blk < 4; blk++) {
                    float4 v[16];
#pragma unroll
                    for (int j = 0; j < 8; j++) {
                        int u = (blk * 8 + j) * 224 + wt;
                        v[2 * j]     = s4[2 * u];
                        v[2 * j + 1] = s4[2 * u + 1];
                    }
#pragma unroll
                    for (int j = 0; j < 8; j++) {
                        int u = (blk * 8 + j) * 224 + wt;
                        __half2 hh[4];
                        hh[0] = __floats2half2_rn(v[2 * j].x,     v[2 * j].y);
                        hh[1] = __floats2half2_rn(v[2 * j].z,     v[2 * j].w);
                        hh[2] = __floats2half2_rn(v[2 * j + 1].x, v[2 * j + 1].y);
                        hh[3] = __floats2half2_rn(v[2 * j + 1].z, v[2 * j + 1].w);
                        d4[u] = *(int4*)hh;
                    }
                }
            } else {
                for (int i = 0; i < 32; i++) {
                    int u = i * 224 + wt;
                    size_t idx = base0 + (size_t)u * 8;
                    if (idx + 8 <= WTOT) cvt8(wsrc, g_wdn, idx);
                }
            }
        }
    }

    // ---- control warp: TMA + MMA pipeline ----
    if (active && warp == 0 && elect1()) {
#pragma unroll
        for (int p = 0; p < 3; p++) {
            uint32_t st = sb + SMA + p * STAGE_BYTES;
            mbar_expect(sb + 8 * p, STAGE_BYTES);
            tma2d(st,        &tmA, p * KC, row0,  sb + 8 * p);
            tma2d(st + A_ST, &tmB, p * KC, brow0, sb + 8 * p);
        }
        for (int s = 0; s < NKC; s++) {
            int slot = s % STG;
            int t = s + 3;
            if (t < NKC) {
                int sl = t % STG;
                if (t >= STG) mbar_wait(sb + 64 + 8 * sl, (uint32_t)(((t - STG) / STG) & 1));
                uint32_t st = sb + SMA + sl * STAGE_BYTES;
                mbar_expect(sb + 8 * sl, STAGE_BYTES);
                tma2d(st,        &tmA, t * KC, row0,  sb + 8 * sl);
                tma2d(st + A_ST, &tmB, t * KC, brow0, sb + 8 * sl);
            }
            mbar_wait(sb + 8 * slot, (uint32_t)((s / STG) & 1));
            uint32_t st = sb + SMA + slot * STAGE_BYTES;
            uint64_t bd = mk_desc64(st + A_ST);
#pragma unroll
            for (int g = 0; g < GM; g++) {
                uint64_t ad = mk_desc64(st + g * 8192);
#pragma unroll
                for (int ks = 0; ks < 2; ks++) {
                    mma_f16_ss(tmem + g * BN, ad + ks * 2, bd + ks * 2, idesc,
                               (uint32_t)((s | ks) != 0));
                }
            }
            tccommit(sb + 64 + 8 * slot);
        }
    }
    __syncthreads();
    if (!active) return;
#pragma unroll
    for (int j = 0; j < STG; j++) {
        int sj = (NKC - 1) - ((NKC - 1 - j) % STG);
        mbar_wait(sb + 64 + 8 * j, (uint32_t)((sj / STG) & 1));
    }
    asm volatile("tcgen05.fence::after_thread_sync;" ::: "memory");

    // ---- epilogue ----
    int g = warp >> 2;
    int sub = warp & 3;
    const float* bp = bias + (size_t)e * NOUT + n0;
    if (g < ng) {
        int row = row0 + g * BM + sub * 32 + lane;
        bool ok = row < row_end;
#pragma unroll
        for (int cb = 0; cb < 8; cb++) {
            uint32_t r[32];
            ldtm32(r, tmem + g * BN + cb * 32);
            asm volatile("tcgen05.wait::ld.sync.aligned;" ::: "memory");
            if (ok) {
                int col = cb * 32;
                if (UP) {
                    __half2 o[16];
#pragma unroll
                    for (int j = 0; j < 16; j++) {
                        float v0 = __uint_as_float(r[2 * j])     + bp[col + 2 * j];
                        float v1 = __uint_as_float(r[2 * j + 1]) + bp[col + 2 * j + 1];
                        v0 = v0 / (1.f + __expf(-v0));
                        v1 = v1 / (1.f + __expf(-v1));
                        o[j] = __floats2half2_rn(v0, v1);
                    }
                    int4* dst = (int4*)(g_h + (size_t)row * HID + n0 + col);
#pragma unroll
                    for (int q = 0; q < 4; q++) dst[q] = ((int4*)o)[q];
                } else {
                    int tok = g_perm[row];
                    float4* dst = (float4*)(out + (size_t)tok * DIM + n0 + col);
#pragma unroll
                    for (int q = 0; q < 8; q++) {
                        float4 ov;
                        ov.x = __uint_as_float(r[4 * q + 0]) + bp[col + 4 * q + 0];
                        ov.y = __uint_as_float(r[4 * q + 1]) + bp[col + 4 * q + 1];
                        ov.z = __uint_as_float(r[4 * q + 2]) + bp[col + 4 * q + 2];
                        ov.w = __uint_as_float(r[4 * q + 3]) + bp[col + 4 * q + 3];
                        dst[q] = ov;
                    }
                }
            }
        }
    }
    __syncthreads();
    if (warp == 0) tmdealloc(tmem, 512);
#endif
}

// ================= wmma fallback GEMMs (active only in non-'a' image) =================
__global__ __launch_bounds__(256, 2) void k_up(const float* __restrict__ Wup,
                                               const float* __restrict__ bup) {
#if !TC5
    __shared__ __align__(128) char smem_raw[4 * BM * LDSMW * sizeof(__half)];
    __half (*sA)[BM][LDSMW] = (__half (*)[BM][LDSMW])smem_raw;
    __half (*sB)[BM][LDSMW] = (__half (*)[BM][LDSMW])(smem_raw + 2 * BM * LDSMW * sizeof(__half));
    float* stage_all = (float*)smem_raw;

    int mt = blockIdx.y;
    int e = g_tile_e[mt];
    if (e < 0) return;
    int row0 = g_tile_r0[mt], row_end = g_off[e + 1];
    int n0 = blockIdx.x * BNW;
    int tid = threadIdx.x, warp = tid >> 5, lane = tid & 31;
    int wm = warp >> 2, wn = warp & 3;

    const __half* Ag = g_xg + (size_t)row0 * DIM;
    const float*  Bg = Wup + (size_t)e * HID * DIM + (size_t)n0 * DIM;

    wmma::fragment<wmma::accumulator, 16, 16, 16, float> c[4][2];
#pragma unroll
    for (int i = 0; i < 4; i++)
#pragma unroll
        for (int j = 0; j < 2; j++) wmma::fill_fragment(c[i][j], 0.f);

    int4 ra[2];
    float4 rb[4];

    auto LOADA = [&](int kt) {
#pragma unroll
        for (int i = 0; i < 2; i++) {
            int q = tid + i * 256, r = q >> 2, c8 = q & 3;
            ra[i] = *(const int4*)(Ag + (size_t)r * DIM + kt * BK + c8 * 8);
        }
    };
    auto LOADB = [&](int kt) {
#pragma unroll
        for (int i = 0; i < 4; i++) {
            int q = tid + i * 256, r = q >> 3, c4 = q & 7;
            rb[i] = *(const float4*)(Bg + (size_t)r * DIM + kt * BK + c4 * 4);
        }
    };
    auto STORE = [&](int buf) {
#pragma unroll
        for (int i = 0; i < 2; i++) {
            int q = tid + i * 256, r = q >> 2, c8 = q & 3;
            *(int4*)&sA[buf][r][c8 * 8] = ra[i];
        }
#pragma unroll
        for (int i = 0; i < 4; i++) {
            int q = tid + i * 256, r = q >> 3, c4 = q & 7;
            *(__half2*)&sB[buf][r][c4 * 4]     = __floats2half2_rn(rb[i].x, rb[i].y);
            *(__half2*)&sB[buf][r][c4 * 4 + 2] = __floats2half2_rn(rb[i].z, rb[i].w);
        }
    };
    auto COMP = [&](int buf) {
#pragma unroll
        for (int ks = 0; ks < 2; ks++) {
            wmma::fragment<wmma::matrix_a, 16, 16, 16, __half, wmma::row_major> a[4];
            wmma::fragment<wmma::matrix_b, 16, 16, 16, __half, wmma::col_major> b[2];
#pragma unroll
            for (int i = 0; i < 4; i++)
                wmma::load_matrix_sync(a[i], &sA[buf][wm * 64 + i * 16][ks * 16], LDSMW);
#pragma unroll
            for (int j = 0; j < 2; j++)
                wmma::load_matrix_sync(b[j], &sB[buf][wn * 32 + j * 16][ks * 16], LDSMW);
#pragma unroll
            for (int i = 0; i < 4; i++)
#pragma unroll
                for (int j = 0; j < 2; j++)
                    wmma::mma_sync(c[i][j], a[i], b[j], c[i][j]);
        }
    };

    LOADA(0); LOADB(0); STORE(0); __syncthreads();
    const int NK = DIM / BK;
    for (int kt = 1; kt < NK; kt++) {
        LOADA(kt); LOADB(kt);
        COMP((kt - 1) & 1);
        STORE(kt & 1);
        __syncthreads();
    }
    COMP((NK - 1) & 1);
    __syncthreads();

    float* st = stage_all + warp * 16 * 20;
#pragma unroll
    for (int i = 0; i < 4; i++)
#pragma unroll
        for (int j = 0; j < 2; j++) {
            wmma::store_matrix_sync(st, c[i][j], 20, wmma::mem_row_major);
            __syncwarp();
            int rr = lane >> 1, cbase = (lane & 1) * 8;
            int grow = row0 + wm * 64 + i * 16 + rr;
            if (grow < row_end) {
                int gcol = n0 + wn * 32 + j * 16 + cbase;
                __half2 o[4];
#pragma unroll
                for (int k2 = 0; k2 < 4; k2++) {
                    float v0 = st[rr * 20 + cbase + 2 * k2]     + bup[(size_t)e * HID + gcol + 2 * k2];
                    float v1 = st[rr * 20 + cbase + 2 * k2 + 1] + bup[(size_t)e * HID + gcol + 2 * k2 + 1];
                    v0 = v0 / (1.f + expf(-v0));
                    v1 = v1 / (1.f + expf(-v1));
                    o[k2] = __floats2half2_rn(v0, v1);
                }
                *(int4*)&g_h[(size_t)grow * HID + gcol] = *(int4*)o;
            }
            __syncwarp();
        }
#endif
}

__global__ __launch_bounds__(256, 2) void k_down(const float* __restrict__ Wdown,
                                                 const float* __restrict__ bdown,
                                                 float* __restrict__ out) {
#if !TC5
    __shared__ __align__(128) char smem_raw[4 * BM * LDSMW * sizeof(__half)];
    __half (*sA)[BM][LDSMW] = (__half (*)[BM][LDSMW])smem_raw;
    __half (*sB)[BM][LDSMW] = (__half (*)[BM][LDSMW])(smem_raw + 2 * BM * LDSMW * sizeof(__half));
    float* stage_all = (float*)smem_raw;

    int mt = blockIdx.y;
    int e = g_tile_e[mt];
    if (e < 0) return;
    int row0 = g_tile_r0[mt], row_end = g_off[e + 1];
    int n0 = blockIdx.x * BNW;
    int tid = threadIdx.x, warp = tid >> 5, lane = tid & 31;
    int wm = warp >> 2, wn = warp & 3;

    const __half* Ag = g_h + (size_t)row0 * HID;
    const float*  Bg = Wdown + (size_t)e * DIM * HID + (size_t)n0 * HID;

    wmma::fragment<wmma::accumulator, 16, 16, 16, float> c[4][2];
#pragma unroll
    for (int i = 0; i < 4; i++)
#pragma unroll
        for (int j = 0; j < 2; j++) wmma::fill_fragment(c[i][j], 0.f);

    int4 ra[2];
    float4 rb[4];

    auto LOADA = [&](int kt) {
#pragma unroll
        for (int i = 0; i < 2; i++) {
            int q = tid + i * 256, r = q >> 2, c8 = q & 3;
            ra[i] = *(const int4*)(Ag + (size_t)r * HID + kt * BK + c8 * 8);
        }
    };
    auto LOADB = [&](int kt) {
#pragma unroll
        for (int i = 0; i < 4; i++) {
            int q = tid + i * 256, r = q >> 3, c4 = q & 7;
            rb[i] = *(const float4*)(Bg + (size_t)r * HID + kt * BK + c4 * 4);
        }
    };
    auto STORE = [&](int buf) {
#pragma unroll
        for (int i = 0; i < 2; i++) {
            int q = tid + i * 256, r = q >> 2, c8 = q & 3;
            *(int4*)&sA[buf][r][c8 * 8] = ra[i];
        }
#pragma unroll
        for (int i = 0; i < 4; i++) {
            int q = tid + i * 256, r = q >> 3, c4 = q & 7;
            *(__half2*)&sB[buf][r][c4 * 4]     = __floats2half2_rn(rb[i].x, rb[i].y);
            *(__half2*)&sB[buf][r][c4 * 4 + 2] = __floats2half2_rn(rb[i].z, rb[i].w);
        }
    };
    auto COMP = [&](int buf) {
#pragma unroll
        for (int ks = 0; ks < 2; ks++) {
            wmma::fragment<wmma::matrix_a, 16, 16, 16, __half, wmma::row_major> a[4];
            wmma::fragment<wmma::matrix_b, 16, 16, 16, __half, wmma::col_major> b[2];
#pragma unroll
            for (int i = 0; i < 4; i++)
                wmma::load_matrix_sync(a[i], &sA[buf][wm * 64 + i * 16][ks * 16], LDSMW);
#pragma unroll
            for (int j = 0; j < 2; j++)
                wmma::load_matrix_sync(b[j], &sB[buf][wn * 32 + j * 16][ks * 16], LDSMW);
#pragma unroll
            for (int i = 0; i < 4; i++)
#pragma unroll
                for (int j = 0; j < 2; j++)
                    wmma::mma_sync(c[i][j], a[i], b[j], c[i][j]);
        }
    };

    LOADA(0); LOADB(0); STORE(0); __syncthreads();
    const int NK = HID / BK;
    for (int kt = 1; kt < NK; kt++) {
        LOADA(kt); LOADB(kt);
        COMP((kt - 1) & 1);
        STORE(kt & 1);
        __syncthreads();
    }
    COMP((NK - 1) & 1);
    __syncthreads();

    float* st = stage_all + warp * 16 * 20;
#pragma unroll
    for (int i = 0; i < 4; i++)
#pragma unroll
        for (int j = 0; j < 2; j++) {
            wmma::store_matrix_sync(st, c[i][j], 20, wmma::mem_row_major);
            __syncwarp();
            int rr = lane >> 1, cbase = (lane & 1) * 8;
            int grow = row0 + wm * 64 + i * 16 + rr;
            if (grow < row_end) {
                int tok = g_perm[grow];
                int gcol = n0 + wn * 32 + j * 16 + cbase;
                float4 o0, o1;
                o0.x = st[rr * 20 + cbase + 0] + bdown[(size_t)e * DIM + gcol + 0];
                o0.y = st[rr * 20 + cbase + 1] + bdown[(size_t)e * DIM + gcol + 1];
                o0.z = st[rr * 20 + cbase + 2] + bdown[(size_t)e * DIM + gcol + 2];
                o0.w = st[rr * 20 + cbase + 3] + bdown[(size_t)e * DIM + gcol + 3];
                o1.x = st[rr * 20 + cbase + 4] + bdown[(size_t)e * DIM + gcol + 4];
                o1.y = st[rr * 20 + cbase + 5] + bdown[(size_t)e * DIM + gcol + 5];
                o1.z = st[rr * 20 + cbase + 6] + bdown[(size_t)e * DIM + gcol + 6];
                o1.w = st[rr * 20 + cbase + 7] + bdown[(size_t)e * DIM + gcol + 7];
                *(float4*)&out[(size_t)tok * DIM + gcol]     = o0;
                *(float4*)&out[(size_t)tok * DIM + gcol + 4] = o1;
            }
            __syncwarp();
        }
#endif
}

// ---------------- host: tensormap encode via dlopen ----------------
typedef CUresult (*encode_fn_t)(CUtensorMap*, CUtensorMapDataType, cuuint32_t, void*,
                                const cuuint64_t*, const cuuint64_t*, const cuuint32_t*,
                                const cuuint32_t*, CUtensorMapInterleave, CUtensorMapSwizzle,
                                CUtensorMapL2promotion, CUtensorMapFloatOOBfill);

static void encode_map(encode_fn_t fn, CUtensorMap* m, void* base,
                       uint64_t d0, uint64_t d1) {
    cuuint64_t dims[2]    = {d0, d1};
    cuuint64_t strides[1] = {d0 * 2};
    cuuint32_t box[2]     = {KC, 256};
    cuuint32_t es[2]      = {1, 1};
    fn(m, CU_TENSOR_MAP_DATA_TYPE_UINT16, 2, base, dims, strides, box, es,
       CU_TENSOR_MAP_INTERLEAVE_NONE, CU_TENSOR_MAP_SWIZZLE_64B,
       CU_TENSOR_MAP_L2_PROMOTION_L2_128B, CU_TENSOR_MAP_FLOAT_OOB_FILL_NONE);
}

// ---------------- launcher ----------------
extern "C" void kernel_launch(void* const* d_in, const int* in_sizes, int n_in,
                              void* d_out, int out_size) {
    const float* x     = (const float*)d_in[0];
    const float* Wr    = (const float*)d_in[1];
    const float* br    = (const float*)d_in[2];
    const float* Wup   = (const float*)d_in[3];
    const float* bup   = (const float*)d_in[4];
    const float* Wdown = (const float*)d_in[5];
    const float* bdown = (const float*)d_in[6];
    float* out = (float*)d_out;

    void* h = dlopen("libcuda.so.1", RTLD_LAZY | RTLD_NOLOAD);
    if (!h) h = dlopen("libcuda.so.1", RTLD_LAZY);
    if (!h) h = dlopen("libcuda.so", RTLD_LAZY);
    encode_fn_t enc = h ? (encode_fn_t)dlsym(h, "cuTensorMapEncodeTiled") : nullptr;

    void *p_xg = nullptr, *p_h = nullptr, *p_wup = nullptr, *p_wdn = nullptr;
    cudaGetSymbolAddress(&p_xg,  g_xg);
    cudaGetSymbolAddress(&p_h,   g_h);
    cudaGetSymbolAddress(&p_wup, g_wup);
    cudaGetSymbolAddress(&p_wdn, g_wdn);

    CUtensorMap tmA_up, tmB_up, tmA_dn, tmB_dn;
    memset(&tmA_up, 0, sizeof(tmA_up));
    memset(&tmB_up, 0, sizeof(tmB_up));
    memset(&tmA_dn, 0, sizeof(tmA_dn));
    memset(&tmB_dn, 0, sizeof(tmB_dn));
    if (enc) {
        encode_map(enc, &tmA_up, p_xg,  DIM, NTOK + PAD);
        encode_map(enc, &tmB_up, p_wup, DIM, (uint64_t)NE * HID);
        encode_map(enc, &tmA_dn, p_h,   HID, NTOK + PAD);
        encode_map(enc, &tmB_dn, p_wdn, HID, (uint64_t)NE * DIM);
    }

    cudaFuncSetAttribute(k_gemm<DIM, true>,  cudaFuncAttributeMaxDynamicSharedMemorySize, SMEM_BYTES);
    cudaFuncSetAttribute(k_gemm<HID, false>, cudaFuncAttributeMaxDynamicSharedMemorySize, SMEM_BYTES);

    k_router<<<NRB, 256>>>(x, Wr, br);                           // + inline last-block scan
    k_gather<<<NRB + NCONV_UP, 256>>>(x, Wup);                   // gather ∥ Wup convert
    k_up<<<dim3(HID / BNW, MAXT), 256>>>(Wup, bup);                                     // empty in 'a'
    k_gemm<DIM, true ><<<dim3(HID / BN, MAXG), 256, SMEM_BYTES>>>(tmA_up, tmB_up, bup, nullptr, Wdown);
    k_gemm<HID, false><<<dim3(DIM / BN, MAXG), 256, SMEM_BYTES>>>(tmA_dn, tmB_dn, bdown, out, nullptr);
    k_down<<<dim3(DIM / BNW, MAXT), 256>>>(Wdown, bdown, out);                          // empty in 'a'
}

// round 16
// speedup vs baseline: 1.0407x; 1.0407x over previous
#include <cuda_runtime.h>
#include <cuda.h>
#include <cuda_fp16.h>
#include <mma.h>
#include <stdint.h>
#include <math.h>
#include <dlfcn.h>
#include <string.h>

using namespace nvcuda;

#define NTOK 8192
#define DIM  1024
#define HID  4096
#define NE   8
#define BM   128
#define BN   256
#define GM   2
#define BNW  128
#define BK   32
#define LDSMW (BK + 8)
#define KC   32
#define STG  6                          // 6 buffers, lookahead 4 (distance-2 done slack kept)
#define LKA  4
#define A_ST (GM * BM * KC * 2)         // 16384
#define B_ST (BN * KC * 2)              // 16384
#define STAGE_BYTES (A_ST + B_ST)       // 32768
#define PAD  (GM*BM)
#define MAXG (NTOK / BM / GM + NE)      // 40
#define MAXT (NTOK / BM + NE)
#define SMEM_BYTES (1024 + 1024 + STG * STAGE_BYTES)   // 198656
#define WTOT ((size_t)NE * HID * DIM)   // 33554432 per weight tensor
#define NCONV_UP 16384
#define NRB (NTOK / 8)
#define SLICE 52432                     // Wdown elems per UP-GEMM CTA
#define SLICE8 (SLICE / 8)              // 6554

#if defined(__CUDA_ARCH_FEAT_SM103_ALL) || defined(__CUDA_ARCH_FEAT_SM100_ALL) || defined(__CUDA_ARCH_FEAT_SM101_ALL)
#define TC5 1
#else
#define TC5 0
#endif

// ---------------- device scratch ----------------
__device__ int    g_expert[NTOK];
__device__ int    g_count[NE];          // zero-init; scan re-zeroes after consuming
__device__ int    g_cursor[NE];
__device__ int    g_done;
__device__ int    g_off[NE + 1];
__device__ int    g_perm[NTOK];
__device__ int    g_grp_e[MAXG];
__device__ int    g_grp_r0[MAXG];
__device__ int    g_grp_ng[MAXG];
__device__ int    g_tile_e[MAXT];
__device__ int    g_tile_r0[MAXT];
__device__ __half g_xg[(size_t)(NTOK + PAD) * DIM];
__device__ __half g_h [(size_t)(NTOK + PAD) * HID];
__device__ __half g_wup[WTOT];
__device__ __half g_wdn[WTOT];

// ---------------- PTX helpers ----------------
__device__ __forceinline__ uint32_t smem_u32(const void* p) {
    uint32_t a;
    asm("{ .reg .u64 t; cvta.to.shared.u64 t, %1; cvt.u32.u64 %0, t; }" : "=r"(a) : "l"(p));
    return a;
}
#if TC5
__device__ __forceinline__ bool elect1() {
    uint32_t r;
    asm volatile("{\n\t.reg .pred p;\n\telect.sync _|p, 0xFFFFFFFF;\n\tselp.b32 %0,1,0,p;\n\t}" : "=r"(r));
    return r != 0;
}
__device__ __forceinline__ void mbar_init(uint32_t a, uint32_t cnt) {
    asm volatile("mbarrier.init.shared.b64 [%0], %1;" :: "r"(a), "r"(cnt) : "memory");
}
__device__ __forceinline__ void mbar_wait(uint32_t a, uint32_t ph) {
    asm volatile(
        "{\n\t.reg .pred P;\n\t"
        "LW_%=:\n\t"
        "mbarrier.try_wait.parity.acquire.cta.shared::cta.b64 P, [%0], %1, 0x989680;\n\t"
        "@P bra LD_%=;\n\t"
        "bra LW_%=;\n\t"
        "LD_%=:\n\t}"
        :: "r"(a), "r"(ph) : "memory");
}
__device__ __forceinline__ void mbar_expect(uint32_t a, uint32_t bytes) {
    asm volatile("mbarrier.arrive.expect_tx.shared.b64 _, [%0], %1;"
                 :: "r"(a), "r"(bytes) : "memory");
}
__device__ __forceinline__ void tma2d(uint32_t dst, const void* map, int x, int y, uint32_t mbar) {
    asm volatile(
        "cp.async.bulk.tensor.2d.shared::cta.global.tile.mbarrier::complete_tx::bytes "
        "[%0], [%1, {%2, %3}], [%4];"
        :: "r"(dst), "l"(map), "r"(x), "r"(y), "r"(mbar) : "memory");
}
__device__ __forceinline__ void tmalloc(uint32_t smem_dst, uint32_t ncols) {
    asm volatile("tcgen05.alloc.cta_group::1.sync.aligned.shared::cta.b32 [%0], %1;"
                 :: "r"(smem_dst), "r"(ncols) : "memory");
}
__device__ __forceinline__ void tmdealloc(uint32_t tmem, uint32_t ncols) {
    asm volatile("tcgen05.relinquish_alloc_permit.cta_group::1.sync.aligned;");
    asm volatile("tcgen05.dealloc.cta_group::1.sync.aligned.b32 %0, %1;" :: "r"(tmem), "r"(ncols));
}
__device__ __forceinline__ void mma_f16_ss(uint32_t d, uint64_t ad, uint64_t bd, uint32_t idesc, uint32_t en) {
    asm volatile(
        "{\n\t.reg .pred p;\n\tsetp.ne.u32 p, %5, 0;\n\t"
        "tcgen05.mma.cta_group::1.kind::f16 [%0], %1, %2, %3, {%4,%4,%4,%4}, p;\n\t}"
        :: "r"(d), "l"(ad), "l"(bd), "r"(idesc), "r"(0u), "r"(en) : "memory");
}
__device__ __forceinline__ void tccommit(uint32_t mbar) {
    asm volatile("tcgen05.commit.cta_group::1.mbarrier::arrive::one.shared::cluster.b64 [%0];"
                 :: "r"(mbar) : "memory");
}
__device__ __forceinline__ void ldtm32(uint32_t* r, uint32_t addr) {
    asm volatile(
        "tcgen05.ld.sync.aligned.32x32b.x32.b32 "
        "{%0, %1, %2, %3, %4, %5, %6, %7, "
        " %8, %9, %10, %11, %12, %13, %14, %15, "
        " %16, %17, %18, %19, %20, %21, %22, %23, "
        " %24, %25, %26, %27, %28, %29, %30, %31}, [%32];"
        : "=r"(r[0]),  "=r"(r[1]),  "=r"(r[2]),  "=r"(r[3]),
          "=r"(r[4]),  "=r"(r[5]),  "=r"(r[6]),  "=r"(r[7]),
          "=r"(r[8]),  "=r"(r[9]),  "=r"(r[10]), "=r"(r[11]),
          "=r"(r[12]), "=r"(r[13]), "=r"(r[14]), "=r"(r[15]),
          "=r"(r[16]), "=r"(r[17]), "=r"(r[18]), "=r"(r[19]),
          "=r"(r[20]), "=r"(r[21]), "=r"(r[22]), "=r"(r[23]),
          "=r"(r[24]), "=r"(r[25]), "=r"(r[26]), "=r"(r[27]),
          "=r"(r[28]), "=r"(r[29]), "=r"(r[30]), "=r"(r[31])
        : "r"(addr));
}
#endif
// SW64 K-major descriptor: layout=4, SBO=32, LBO=1
__device__ __forceinline__ uint64_t mk_desc64(uint32_t addr) {
    return ((uint64_t)4 << 61) | ((uint64_t)1 << 46) | ((uint64_t)32 << 32) |
           ((uint64_t)1 << 16) | ((addr >> 4) & 0x3FFF);
}

__device__ __forceinline__ void cvt8(const float* src, __half* dst, size_t off) {
    float4 v0 = *(const float4*)(src + off);
    float4 v1 = *(const float4*)(src + off + 4);
    __half2 h[4];
    h[0] = __floats2half2_rn(v0.x, v0.y);
    h[1] = __floats2half2_rn(v0.z, v0.w);
    h[2] = __floats2half2_rn(v1.x, v1.y);
    h[3] = __floats2half2_rn(v1.z, v1.w);
    *(int4*)(dst + off) = *(int4*)h;
}

// ---------------- router + last-block inline scan (self-resetting) ----------------
__global__ void k_router(const float* __restrict__ x,
                         const float* __restrict__ Wr,
                         const float* __restrict__ br) {
    __shared__ float sW[NE * DIM];
    for (int i = threadIdx.x; i < NE * DIM; i += 256) sW[i] = Wr[i];
    __syncthreads();

    int warp = threadIdx.x >> 5, lane = threadIdx.x & 31;
    int t = blockIdx.x * 8 + warp;
    const float4* xr = (const float4*)(x + (size_t)t * DIM);

    float acc[NE];
#pragma unroll
    for (int e = 0; e < NE; e++) acc[e] = 0.f;
#pragma unroll
    for (int p = 0; p < 8; p++) {
        float4 v = xr[p * 32 + lane];
        int c = (p * 32 + lane) * 4;
#pragma unroll
        for (int e = 0; e < NE; e++) {
            const float* w = &sW[e * DIM + c];
            acc[e] += v.x * w[0] + v.y * w[1] + v.z * w[2] + v.w * w[3];
        }
    }
#pragma unroll
    for (int e = 0; e < NE; e++)
#pragma unroll
        for (int o = 16; o; o >>= 1) acc[e] += __shfl_xor_sync(0xffffffffu, acc[e], o);

    if (lane == 0) {
        int best = 0;
        float bv = acc[0] + br[0];
#pragma unroll
        for (int e = 1; e < NE; e++) {
            float v = acc[e] + br[e];
            if (v > bv) { bv = v; best = e; }
        }
        g_expert[t] = best;
        atomicAdd(&g_count[best], 1);
    }
    __syncthreads();
    if (threadIdx.x == 0) {
        __threadfence();
        int tk = atomicAdd(&g_done, 1);
        if (tk == NRB - 1) {
            int cnt[NE];
            int o = 0;
#pragma unroll
            for (int e = 0; e < NE; e++) {
                cnt[e] = g_count[e];
                g_off[e] = o;
                o += cnt[e];
            }
            g_off[NE] = o;
            int tg = 0;
            for (int e = 0; e < NE; e++) {
                int tiles = (cnt[e] + BM - 1) / BM;
                for (int m = 0; m < tiles; m += GM) {
                    g_grp_e[tg] = e;
                    g_grp_r0[tg] = g_off[e] + m * BM;
                    int rem = tiles - m;
                    g_grp_ng[tg] = rem < GM ? rem : GM;
                    tg++;
                }
            }
            for (; tg < MAXG; tg++) g_grp_e[tg] = -1;
            int tt = 0;
            for (int e = 0; e < NE; e++) {
                int tiles = (cnt[e] + BM - 1) / BM;
                for (int m = 0; m < tiles; m++) {
                    g_tile_e[tt] = e;
                    g_tile_r0[tt] = g_off[e] + m * BM;
                    tt++;
                }
            }
            for (; tt < MAXT; tt++) g_tile_e[tt] = -1;
#pragma unroll
            for (int e = 0; e < NE; e++) { g_count[e] = 0; g_cursor[e] = 0; }
            g_done = 0;
            __threadfence();
        }
    }
}

// ---------------- gather (blocks 0..NRB-1) + Wup convert (blocks behind) ----------------
__global__ void k_gather(const float* __restrict__ x, const float* __restrict__ Wup) {
    if (blockIdx.x >= NRB) {
        size_t base = ((size_t)(blockIdx.x - NRB) * 256 + threadIdx.x) * 8;
        cvt8(Wup, g_wup, base);
        return;
    }
    int gw = (blockIdx.x * blockDim.x + threadIdx.x) >> 5;
    int lane = threadIdx.x & 31;
    if (gw >= NTOK) return;
    int t = gw, e = g_expert[t];
    int slot = 0;
    if (lane == 0) {
        int r = atomicAdd(&g_cursor[e], 1);
        slot = g_off[e] + r;
        g_perm[slot] = t;
    }
    slot = __shfl_sync(0xffffffffu, slot, 0);
    const float4* src = (const float4*)(x + (size_t)t * DIM);
    __half2* dst = (__half2*)(g_xg + (size_t)slot * DIM);
#pragma unroll
    for (int p = 0; p < 8; p++) {
        float4 v = src[p * 32 + lane];
        dst[(p * 32 + lane) * 2]     = __floats2half2_rn(v.x, v.y);
        dst[(p * 32 + lane) * 2 + 1] = __floats2half2_rn(v.z, v.w);
    }
}

// ================= TMA tcgen05 GEMM: 6-buffer lookahead-4, + Wdown convert (UP) =================
template<int KTOT, bool UP>
__global__ void __launch_bounds__(256, 1) k_gemm(const __grid_constant__ CUtensorMap tmA,
                                                 const __grid_constant__ CUtensorMap tmB,
                                                 const float* __restrict__ bias,
                                                 float* __restrict__ out,
                                                 const float* __restrict__ wsrc) {
#if TC5
    extern __shared__ char smem_raw[];
    char* smem = (char*)(((uintptr_t)smem_raw + 1023) & ~(uintptr_t)1023);
    const int NOUT = UP ? HID : DIM;

    int gi = blockIdx.y;
    int e = g_grp_e[gi];
    bool active = (e >= 0);
    if (!UP && !active) return;
    int row0 = active ? g_grp_r0[gi] : 0;
    int ng   = active ? g_grp_ng[gi] : 0;
    int row_end = active ? g_off[e + 1] : 0;
    int n0 = blockIdx.x * BN;
    int tid = threadIdx.x, warp = tid >> 5, lane = tid & 31;
    uint32_t sb = smem_u32(smem);

    if (active) {
        if (tid == 0) {
#pragma unroll
            for (int j = 0; j < STG; j++) {
                mbar_init(sb + 8 * j, 1);            // full
                mbar_init(sb + 64 + 8 * j, 1);       // done
            }
        }
        if (warp == 0) tmalloc(sb + 128, 512);
    }
    __syncthreads();
    uint32_t tmem = 0;
    if (active)
        asm volatile("ld.shared.b32 %0, [%1];" : "=r"(tmem) : "r"(sb + 128));

    const uint32_t idesc = (1u << 4) | ((BN / 8) << 17) | ((BM / 16) << 24);
    const int SMA = 1024;
    const int NKC = KTOT / KC;
    const int brow0 = e * NOUT + n0;

    // ---- background duty (UP only): warps 1-7 convert this CTA's Wdown slice ----
    if (UP && warp != 0) {
        int cta = blockIdx.y * gridDim.x + blockIdx.x;
        size_t base0 = (size_t)cta * SLICE;
        int wt = tid - 32;
#pragma unroll 5
        for (int i = 0; i < 30; i++) {
            int u = i * 224 + wt;
            size_t idx = base0 + (size_t)u * 8;
            if (u < SLICE8 && idx + 8 <= WTOT)
                cvt8(wsrc, g_wdn, idx);
        }
    }

    // ---- control warp: TMA + MMA pipeline (lookahead 4, done-slack 2) ----
    if (active && warp == 0 && elect1()) {
#pragma unroll
        for (int p = 0; p < LKA; p++) {
            uint32_t st = sb + SMA + p * STAGE_BYTES;
            mbar_expect(sb + 8 * p, STAGE_BYTES);
            tma2d(st,        &tmA, p * KC, row0,  sb + 8 * p);
            tma2d(st + A_ST, &tmB, p * KC, brow0, sb + 8 * p);
        }
        for (int s = 0; s < NKC; s++) {
            int slot = s % STG;
            int t = s + LKA;
            if (t < NKC) {
                int sl = t % STG;
                if (t >= STG) mbar_wait(sb + 64 + 8 * sl, (uint32_t)(((t - STG) / STG) & 1));
                uint32_t st = sb + SMA + sl * STAGE_BYTES;
                mbar_expect(sb + 8 * sl, STAGE_BYTES);
                tma2d(st,        &tmA, t * KC, row0,  sb + 8 * sl);
                tma2d(st + A_ST, &tmB, t * KC, brow0, sb + 8 * sl);
            }
            mbar_wait(sb + 8 * slot, (uint32_t)((s / STG) & 1));
            uint32_t st = sb + SMA + slot * STAGE_BYTES;
            uint64_t bd = mk_desc64(st + A_ST);
#pragma unroll
            for (int g = 0; g < GM; g++) {
                uint64_t ad = mk_desc64(st + g * 8192);
#pragma unroll
                for (int ks = 0; ks < 2; ks++) {
                    mma_f16_ss(tmem + g * BN, ad + ks * 2, bd + ks * 2, idesc,
                               (uint32_t)((s | ks) != 0));
                }
            }
            tccommit(sb + 64 + 8 * slot);
        }
    }
    __syncthreads();
    if (!active) return;
#pragma unroll
    for (int j = 0; j < STG; j++) {
        int sj = (NKC - 1) - ((NKC - 1 - j) % STG);
        mbar_wait(sb + 64 + 8 * j, (uint32_t)((sj / STG) & 1));
    }
    asm volatile("tcgen05.fence::after_thread_sync;" ::: "memory");

    // ---- epilogue ----
    int g = warp >> 2;
    int sub = warp & 3;
    const float* bp = bias + (size_t)e * NOUT + n0;
    if (g < ng) {
        int row = row0 + g * BM + sub * 32 + lane;
        bool ok = row < row_end;
#pragma unroll
        for (int cb = 0; cb < 8; cb++) {
            uint32_t r[32];
            ldtm32(r, tmem + g * BN + cb * 32);
            asm volatile("tcgen05.wait::ld.sync.aligned;" ::: "memory");
            if (ok) {
                int col = cb * 32;
                if (UP) {
                    __half2 o[16];
#pragma unroll
                    for (int j = 0; j < 16; j++) {
                        float v0 = __uint_as_float(r[2 * j])     + bp[col + 2 * j];
                        float v1 = __uint_as_float(r[2 * j + 1]) + bp[col + 2 * j + 1];
                        v0 = v0 / (1.f + __expf(-v0));
                        v1 = v1 / (1.f + __expf(-v1));
                        o[j] = __floats2half2_rn(v0, v1);
                    }
                    int4* dst = (int4*)(g_h + (size_t)row * HID + n0 + col);
#pragma unroll
                    for (int q = 0; q < 4; q++) dst[q] = ((int4*)o)[q];
                } else {
                    int tok = g_perm[row];
                    float4* dst = (float4*)(out + (size_t)tok * DIM + n0 + col);
#pragma unroll
                    for (int q = 0; q < 8; q++) {
                        float4 ov;
                        ov.x = __uint_as_float(r[4 * q + 0]) + bp[col + 4 * q + 0];
                        ov.y = __uint_as_float(r[4 * q + 1]) + bp[col + 4 * q + 1];
                        ov.z = __uint_as_float(r[4 * q + 2]) + bp[col + 4 * q + 2];
                        ov.w = __uint_as_float(r[4 * q + 3]) + bp[col + 4 * q + 3];
                        dst[q] = ov;
                    }
                }
            }
        }
    }
    __syncthreads();
    if (warp == 0) tmdealloc(tmem, 512);
#endif
}

// ================= wmma fallback GEMMs (active only in non-'a' image) =================
__global__ __launch_bounds__(256, 2) void k_up(const float* __restrict__ Wup,
                                               const float* __restrict__ bup) {
#if !TC5
    __shared__ __align__(128) char smem_raw[4 * BM * LDSMW * sizeof(__half)];
    __half (*sA)[BM][LDSMW] = (__half (*)[BM][LDSMW])smem_raw;
    __half (*sB)[BM][LDSMW] = (__half (*)[BM][LDSMW])(smem_raw + 2 * BM * LDSMW * sizeof(__half));
    float* stage_all = (float*)smem_raw;

    int mt = blockIdx.y;
    int e = g_tile_e[mt];
    if (e < 0) return;
    int row0 = g_tile_r0[mt], row_end = g_off[e + 1];
    int n0 = blockIdx.x * BNW;
    int tid = threadIdx.x, warp = tid >> 5, lane = tid & 31;
    int wm = warp >> 2, wn = warp & 3;

    const __half* Ag = g_xg + (size_t)row0 * DIM;
    const float*  Bg = Wup + (size_t)e * HID * DIM + (size_t)n0 * DIM;

    wmma::fragment<wmma::accumulator, 16, 16, 16, float> c[4][2];
#pragma unroll
    for (int i = 0; i < 4; i++)
#pragma unroll
        for (int j = 0; j < 2; j++) wmma::fill_fragment(c[i][j], 0.f);

    int4 ra[2];
    float4 rb[4];

    auto LOADA = [&](int kt) {
#pragma unroll
        for (int i = 0; i < 2; i++) {
            int q = tid + i * 256, r = q >> 2, c8 = q & 3;
            ra[i] = *(const int4*)(Ag + (size_t)r * DIM + kt * BK + c8 * 8);
        }
    };
    auto LOADB = [&](int kt) {
#pragma unroll
        for (int i = 0; i < 4; i++) {
            int q = tid + i * 256, r = q >> 3, c4 = q & 7;
            rb[i] = *(const float4*)(Bg + (size_t)r * DIM + kt * BK + c4 * 4);
        }
    };
    auto STORE = [&](int buf) {
#pragma unroll
        for (int i = 0; i < 2; i++) {
            int q = tid + i * 256, r = q >> 2, c8 = q & 3;
            *(int4*)&sA[buf][r][c8 * 8] = ra[i];
        }
#pragma unroll
        for (int i = 0; i < 4; i++) {
            int q = tid + i * 256, r = q >> 3, c4 = q & 7;
            *(__half2*)&sB[buf][r][c4 * 4]     = __floats2half2_rn(rb[i].x, rb[i].y);
            *(__half2*)&sB[buf][r][c4 * 4 + 2] = __floats2half2_rn(rb[i].z, rb[i].w);
        }
    };
    auto COMP = [&](int buf) {
#pragma unroll
        for (int ks = 0; ks < 2; ks++) {
            wmma::fragment<wmma::matrix_a, 16, 16, 16, __half, wmma::row_major> a[4];
            wmma::fragment<wmma::matrix_b, 16, 16, 16, __half, wmma::col_major> b[2];
#pragma unroll
            for (int i = 0; i < 4; i++)
                wmma::load_matrix_sync(a[i], &sA[buf][wm * 64 + i * 16][ks * 16], LDSMW);
#pragma unroll
            for (int j = 0; j < 2; j++)
                wmma::load_matrix_sync(b[j], &sB[buf][wn * 32 + j * 16][ks * 16], LDSMW);
#pragma unroll
            for (int i = 0; i < 4; i++)
#pragma unroll
                for (int j = 0; j < 2; j++)
                    wmma::mma_sync(c[i][j], a[i], b[j], c[i][j]);
        }
    };

    LOADA(0); LOADB(0); STORE(0); __syncthreads();
    const int NK = DIM / BK;
    for (int kt = 1; kt < NK; kt++) {
        LOADA(kt); LOADB(kt);
        COMP((kt - 1) & 1);
        STORE(kt & 1);
        __syncthreads();
    }
    COMP((NK - 1) & 1);
    __syncthreads();

    float* st = stage_all + warp * 16 * 20;
#pragma unroll
    for (int i = 0; i < 4; i++)
#pragma unroll
        for (int j = 0; j < 2; j++) {
            wmma::store_matrix_sync(st, c[i][j], 20, wmma::mem_row_major);
            __syncwarp();
            int rr = lane >> 1, cbase = (lane & 1) * 8;
            int grow = row0 + wm * 64 + i * 16 + rr;
            if (grow < row_end) {
                int gcol = n0 + wn * 32 + j * 16 + cbase;
                __half2 o[4];
#pragma unroll
                for (int k2 = 0; k2 < 4; k2++) {
                    float v0 = st[rr * 20 + cbase + 2 * k2]     + bup[(size_t)e * HID + gcol + 2 * k2];
                    float v1 = st[rr * 20 + cbase + 2 * k2 + 1] + bup[(size_t)e * HID + gcol + 2 * k2 + 1];
                    v0 = v0 / (1.f + expf(-v0));
                    v1 = v1 / (1.f + expf(-v1));
                    o[k2] = __floats2half2_rn(v0, v1);
                }
                *(int4*)&g_h[(size_t)grow * HID + gcol] = *(int4*)o;
            }
            __syncwarp();
        }
#endif
}

__global__ __launch_bounds__(256, 2) void k_down(const float* __restrict__ Wdown,
                                                 const float* __restrict__ bdown,
                                                 float* __restrict__ out) {
#if !TC5
    __shared__ __align__(128) char smem_raw[4 * BM * LDSMW * sizeof(__half)];
    __half (*sA)[BM][LDSMW] = (__half (*)[BM][LDSMW])smem_raw;
    __half (*sB)[BM][LDSMW] = (__half (*)[BM][LDSMW])(smem_raw + 2 * BM * LDSMW * sizeof(__half));
    float* stage_all = (float*)smem_raw;

    int mt = blockIdx.y;
    int e = g_tile_e[mt];
    if (e < 0) return;
    int row0 = g_tile_r0[mt], row_end = g_off[e + 1];
    int n0 = blockIdx.x * BNW;
    int tid = threadIdx.x, warp = tid >> 5, lane = tid & 31;
    int wm = warp >> 2, wn = warp & 3;

    const __half* Ag = g_h + (size_t)row0 * HID;
    const float*  Bg = Wdown + (size_t)e * DIM * HID + (size_t)n0 * HID;

    wmma::fragment<wmma::accumulator, 16, 16, 16, float> c[4][2];
#pragma unroll
    for (int i = 0; i < 4; i++)
#pragma unroll
        for (int j = 0; j < 2; j++) wmma::fill_fragment(c[i][j], 0.f);

    int4 ra[2];
    float4 rb[4];

    auto LOADA = [&](int kt) {
#pragma unroll
        for (int i = 0; i < 2; i++) {
            int q = tid + i * 256, r = q >> 2, c8 = q & 3;
            ra[i] = *(const int4*)(Ag + (size_t)r * HID + kt * BK + c8 * 8);
        }
    };
    auto LOADB = [&](int kt) {
#pragma unroll
        for (int i = 0; i < 4; i++) {
            int q = tid + i * 256, r = q >> 3, c4 = q & 7;
            rb[i] = *(const float4*)(Bg + (size_t)r * HID + kt * BK + c4 * 4);
        }
    };
    auto STORE = [&](int buf) {
#pragma unroll
        for (int i = 0; i < 2; i++) {
            int q = tid + i * 256, r = q >> 2, c8 = q & 3;
            *(int4*)&sA[buf][r][c8 * 8] = ra[i];
        }
#pragma unroll
        for (int i = 0; i < 4; i++) {
            int q = tid + i * 256, r = q >> 3, c4 = q & 7;
            *(__half2*)&sB[buf][r][c4 * 4]     = __floats2half2_rn(rb[i].x, rb[i].y);
            *(__half2*)&sB[buf][r][c4 * 4 + 2] = __floats2half2_rn(rb[i].z, rb[i].w);
        }
    };
    auto COMP = [&](int buf) {
#pragma unroll
        for (int ks = 0; ks < 2; ks++) {
            wmma::fragment<wmma::matrix_a, 16, 16, 16, __half, wmma::row_major> a[4];
            wmma::fragment<wmma::matrix_b, 16, 16, 16, __half, wmma::col_major> b[2];
#pragma unroll
            for (int i = 0; i < 4; i++)
                wmma::load_matrix_sync(a[i], &sA[buf][wm * 64 + i * 16][ks * 16], LDSMW);
#pragma unroll
            for (int j = 0; j < 2; j++)
                wmma::load_matrix_sync(b[j], &sB[buf][wn * 32 + j * 16][ks * 16], LDSMW);
#pragma unroll
            for (int i = 0; i < 4; i++)
#pragma unroll
                for (int j = 0; j < 2; j++)
                    wmma::mma_sync(c[i][j], a[i], b[j], c[i][j]);
        }
    };

    LOADA(0); LOADB(0); STORE(0); __syncthreads();
    const int NK = HID / BK;
    for (int kt = 1; kt < NK; kt++) {
        LOADA(kt); LOADB(kt);
        COMP((kt - 1) & 1);
        STORE(kt & 1);
        __syncthreads();
    }
    COMP((NK - 1) & 1);
    __syncthreads();

    float* st = stage_all + warp * 16 * 20;
#pragma unroll
    for (int i = 0; i < 4; i++)
#pragma unroll
        for (int j = 0; j < 2; j++) {
            wmma::store_matrix_sync(st, c[i][j], 20, wmma::mem_row_major);
            __syncwarp();
            int rr = lane >> 1, cbase = (lane & 1) * 8;
            int grow = row0 + wm * 64 + i * 16 + rr;
            if (grow < row_end) {
                int tok = g_perm[grow];
                int gcol = n0 + wn * 32 + j * 16 + cbase;
                float4 o0, o1;
                o0.x = st[rr * 20 + cbase + 0] + bdown[(size_t)e * DIM + gcol + 0];
                o0.y = st[rr * 20 + cbase + 1] + bdown[(size_t)e * DIM + gcol + 1];
                o0.z = st[rr * 20 + cbase + 2] + bdown[(size_t)e * DIM + gcol + 2];
                o0.w = st[rr * 20 + cbase + 3] + bdown[(size_t)e * DIM + gcol + 3];
                o1.x = st[rr * 20 + cbase + 4] + bdown[(size_t)e * DIM + gcol + 4];
                o1.y = st[rr * 20 + cbase + 5] + bdown[(size_t)e * DIM + gcol + 5];
                o1.z = st[rr * 20 + cbase + 6] + bdown[(size_t)e * DIM + gcol + 6];
                o1.w = st[rr * 20 + cbase + 7] + bdown[(size_t)e * DIM + gcol + 7];
                *(float4*)&out[(size_t)tok * DIM + gcol]     = o0;
                *(float4*)&out[(size_t)tok * DIM + gcol + 4] = o1;
            }
            __syncwarp();
        }
#endif
}

// ---------------- host: tensormap encode via dlopen ----------------
typedef CUresult (*encode_fn_t)(CUtensorMap*, CUtensorMapDataType, cuuint32_t, void*,
                                const cuuint64_t*, const cuuint64_t*, const cuuint32_t*,
                                const cuuint32_t*, CUtensorMapInterleave, CUtensorMapSwizzle,
                                CUtensorMapL2promotion, CUtensorMapFloatOOBfill);

static void encode_map(encode_fn_t fn, CUtensorMap* m, void* base,
                       uint64_t d0, uint64_t d1) {
    cuuint64_t dims[2]    = {d0, d1};
    cuuint64_t strides[1] = {d0 * 2};
    cuuint32_t box[2]     = {KC, 256};
    cuuint32_t es[2]      = {1, 1};
    fn(m, CU_TENSOR_MAP_DATA_TYPE_UINT16, 2, base, dims, strides, box, es,
       CU_TENSOR_MAP_INTERLEAVE_NONE, CU_TENSOR_MAP_SWIZZLE_64B,
       CU_TENSOR_MAP_L2_PROMOTION_L2_128B, CU_TENSOR_MAP_FLOAT_OOB_FILL_NONE);
}

// ---------------- launcher ----------------
extern "C" void kernel_launch(void* const* d_in, const int* in_sizes, int n_in,
                              void* d_out, int out_size) {
    const float* x     = (const float*)d_in[0];
    const float* Wr    = (const float*)d_in[1];
    const float* br    = (const float*)d_in[2];
    const float* Wup   = (const float*)d_in[3];
    const float* bup   = (const float*)d_in[4];
    const float* Wdown = (const float*)d_in[5];
    const float* bdown = (const float*)d_in[6];
    float* out = (float*)d_out;

    void* h = dlopen("libcuda.so.1", RTLD_LAZY | RTLD_NOLOAD);
    if (!h) h = dlopen("libcuda.so.1", RTLD_LAZY);
    if (!h) h = dlopen("libcuda.so", RTLD_LAZY);
    encode_fn_t enc = h ? (encode_fn_t)dlsym(h, "cuTensorMapEncodeTiled") : nullptr;

    void *p_xg = nullptr, *p_h = nullptr, *p_wup = nullptr, *p_wdn = nullptr;
    cudaGetSymbolAddress(&p_xg,  g_xg);
    cudaGetSymbolAddress(&p_h,   g_h);
    cudaGetSymbolAddress(&p_wup, g_wup);
    cudaGetSymbolAddress(&p_wdn, g_wdn);

    CUtensorMap tmA_up, tmB_up, tmA_dn, tmB_dn;
    memset(&tmA_up, 0, sizeof(tmA_up));
    memset(&tmB_up, 0, sizeof(tmB_up));
    memset(&tmA_dn, 0, sizeof(tmA_dn));
    memset(&tmB_dn, 0, sizeof(tmB_dn));
    if (enc) {
        encode_map(enc, &tmA_up, p_xg,  DIM, NTOK + PAD);
        encode_map(enc, &tmB_up, p_wup, DIM, (uint64_t)NE * HID);
        encode_map(enc, &tmA_dn, p_h,   HID, NTOK + PAD);
        encode_map(enc, &tmB_dn, p_wdn, HID, (uint64_t)NE * DIM);
    }

    cudaFuncSetAttribute(k_gemm<DIM, true>,  cudaFuncAttributeMaxDynamicSharedMemorySize, SMEM_BYTES);
    cudaFuncSetAttribute(k_gemm<HID, false>, cudaFuncAttributeMaxDynamicSharedMemorySize, SMEM_BYTES);

    k_router<<<NRB, 256>>>(x, Wr, br);                           // + inline last-block scan
    k_gather<<<NRB + NCONV_UP, 256>>>(x, Wup);                   // gather ∥ Wup convert
    k_up<<<dim3(HID / BNW, MAXT), 256>>>(Wup, bup);                                     // empty in 'a'
    k_gemm<DIM, true ><<<dim3(HID / BN, MAXG), 256, SMEM_BYTES>>>(tmA_up, tmB_up, bup, nullptr, Wdown);
    k_gemm<HID, false><<<dim3(DIM / BN, MAXG), 256, SMEM_BYTES>>>(tmA_dn, tmB_dn, bdown, out, nullptr);
    k_down<<<dim3(DIM / BNW, MAXT), 256>>>(Wdown, bdown, out);                          // empty in 'a'
}